// round 4
// baseline (speedup 1.0000x reference)
#include <cuda_runtime.h>
#include <cuda_bf16.h>
#include <math.h>
#include <stdint.h>

#define NH   16
#define NKV  4
#define HD   128
#define HIDD 2048
#define FFI  8192
#define QKVW ((NH + 2*NKV) * HD)   /* 3072 */
#define NEGV -1e30f

// ================= scratch (B=4, S=1024) =================
static __device__ float g_qkv[4096L * QKVW];
static __device__ float g_scores[(long)4 * NH * 1024 * 1024];
static __device__ float g_attnout[4096L * HIDD];
static __device__ float g_h1[4096L * HIDD];
static __device__ float g_gu[4096L * 2 * FFI];

static __device__ __nv_bfloat16 g_hh[4096L * HIDD],  g_hl[4096L * HIDD];
static __device__ __nv_bfloat16 g_aoh[4096L * HIDD], g_aol[4096L * HIDD];
static __device__ __nv_bfloat16 g_acth[4096L * FFI], g_actl[4096L * FFI];
static __device__ __nv_bfloat16 g_wqkvTh[(long)QKVW * HIDD], g_wqkvTl[(long)QKVW * HIDD];
static __device__ __nv_bfloat16 g_woTh[(long)HIDD * HIDD],   g_woTl[(long)HIDD * HIDD];
static __device__ __nv_bfloat16 g_guTh[(long)2*FFI * HIDD],  g_guTl[(long)2*FFI * HIDD];
static __device__ __nv_bfloat16 g_dnTh[(long)HIDD * FFI],    g_dnTl[(long)HIDD * FFI];

// ================= PTX helpers =================
__device__ __forceinline__ uint32_t smem_u32(const void* p) {
    uint32_t a;
    asm("{ .reg .u64 t; cvta.to.shared.u64 t, %1; cvt.u32.u64 %0, t; }" : "=r"(a) : "l"(p));
    return a;
}
__device__ __forceinline__ void cp16(uint32_t dst, const void* src) {
    asm volatile("cp.async.cg.shared.global [%0], [%1], 16;" :: "r"(dst), "l"(src));
}
__device__ __forceinline__ void cp_commit() { asm volatile("cp.async.commit_group;"); }
__device__ __forceinline__ void cp_wait1() { asm volatile("cp.async.wait_group 1;"); }
__device__ __forceinline__ void cp_wait0() { asm volatile("cp.async.wait_group 0;"); }

__device__ __forceinline__ void ldm_x4(uint32_t* r, uint32_t addr) {
    asm volatile("ldmatrix.sync.aligned.m8n8.x4.shared.b16 {%0,%1,%2,%3}, [%4];"
        : "=r"(r[0]), "=r"(r[1]), "=r"(r[2]), "=r"(r[3]) : "r"(addr));
}
__device__ __forceinline__ void mma16816(float* d, const uint32_t* a, const uint32_t* b) {
    asm volatile("mma.sync.aligned.m16n8k16.row.col.f32.bf16.bf16.f32 "
        "{%0,%1,%2,%3}, {%4,%5,%6,%7}, {%8,%9}, {%0,%1,%2,%3};"
        : "+f"(d[0]), "+f"(d[1]), "+f"(d[2]), "+f"(d[3])
        : "r"(a[0]), "r"(a[1]), "r"(a[2]), "r"(a[3]), "r"(b[0]), "r"(b[1]));
}

// ================= HMMA TN GEMM (bf16x3, fp32 accum) =================
// C[M,N] = Ahi/lo[M,K] x (Bhi/lo[N,K])^T  (+ residual R).
// CTA tile 128x128, BK=64, 8 warps (2x4), warp tile 64x32.
#define SAS 72                               /* smem row stride in bf16 elems */
#define TILEB (128 * SAS * 2)                /* 18432 B per tile */
#define STAGE (4 * TILEB)                    /* Ahi Alo Bhi Blo */
#define HG_SMEM (2 * STAGE)                  /* 147456 B */

template<bool RES>
__global__ void __launch_bounds__(256, 1)
hgemm(const __nv_bfloat16* __restrict__ Ahi, const __nv_bfloat16* __restrict__ Alo,
      const __nv_bfloat16* __restrict__ Bhi, const __nv_bfloat16* __restrict__ Blo,
      const float* __restrict__ R, float* __restrict__ C, int K, int N)
{
    extern __shared__ char sm[];
    const uint32_t sbase = smem_u32(sm);
    const int tid = threadIdx.x;
    const int m0 = blockIdx.x * 128, n0 = blockIdx.y * 128;
    const int wid = tid >> 5, lane = tid & 31;
    const int wm = (wid >> 2) * 64;     // warp row offset (0 / 64)
    const int wn = (wid & 3) * 32;      // warp col offset (0/32/64/96)

    const __nv_bfloat16* srcs[4] = {
        Ahi + (long)m0 * K, Alo + (long)m0 * K,
        Bhi + (long)n0 * K, Blo + (long)n0 * K };

    // ldmatrix per-thread address components
    const int alr = lane & 15, alc = (lane >> 4) * 8;          // A: rows m, col half
    const int blr = lane & 7;
    const int bhalf = (lane >> 3) & 1;                          // k half (0/8)
    const int bquad = (lane >> 4) * 8;                          // n half (0/8)

    float acc[4][4][4];
    #pragma unroll
    for (int i = 0; i < 4; i++)
        #pragma unroll
        for (int j = 0; j < 4; j++)
            #pragma unroll
            for (int q = 0; q < 4; q++) acc[i][j][q] = 0.f;

    const int NB = K >> 6;

    auto load_stage = [&](int s, int blk) {
        const long kb = (long)blk << 6;
        #pragma unroll
        for (int t = 0; t < 4; t++) {
            const __nv_bfloat16* S = srcs[t] + kb;
            const uint32_t dbase = sbase + s * STAGE + t * TILEB;
            #pragma unroll
            for (int i = 0; i < 4; i++) {
                int idx = tid + 256 * i;
                int r = idx >> 3, c = idx & 7;
                cp16(dbase + (r * SAS + c * 8) * 2, S + (long)r * K + c * 8);
            }
        }
        cp_commit();
    };

    load_stage(0, 0);

    for (int blk = 0; blk < NB; blk++) {
        const int s = blk & 1;
        if (blk + 1 < NB) { load_stage(s ^ 1, blk + 1); cp_wait1(); }
        else              { cp_wait0(); }
        __syncthreads();

        const uint32_t sAh = sbase + s * STAGE;
        const uint32_t sAl = sAh + TILEB;
        const uint32_t sBh = sAh + 2 * TILEB;
        const uint32_t sBl = sAh + 3 * TILEB;

        #pragma unroll
        for (int kt = 0; kt < 4; kt++) {
            uint32_t ah[4][4], al[4][4], bh[4][2], bl[4][2];
            #pragma unroll
            for (int ma = 0; ma < 4; ma++) {
                uint32_t ao = ((wm + ma * 16 + alr) * SAS + kt * 16 + alc) * 2;
                ldm_x4(ah[ma], sAh + ao);
                ldm_x4(al[ma], sAl + ao);
            }
            #pragma unroll
            for (int np = 0; np < 2; np++) {
                uint32_t bo = ((wn + np * 16 + bquad + blr) * SAS + kt * 16 + bhalf * 8) * 2;
                uint32_t t4[4];
                ldm_x4(t4, sBh + bo);
                bh[np*2+0][0] = t4[0]; bh[np*2+0][1] = t4[1];
                bh[np*2+1][0] = t4[2]; bh[np*2+1][1] = t4[3];
                ldm_x4(t4, sBl + bo);
                bl[np*2+0][0] = t4[0]; bl[np*2+0][1] = t4[1];
                bl[np*2+1][0] = t4[2]; bl[np*2+1][1] = t4[3];
            }
            #pragma unroll
            for (int ma = 0; ma < 4; ma++)
                #pragma unroll
                for (int na = 0; na < 4; na++) {
                    mma16816(acc[ma][na], ah[ma], bh[na]);
                    mma16816(acc[ma][na], ah[ma], bl[na]);
                    mma16816(acc[ma][na], al[ma], bh[na]);
                }
        }
        __syncthreads();
    }

    // epilogue
    const int erow = lane >> 2, ecol = (lane & 3) * 2;
    #pragma unroll
    for (int ma = 0; ma < 4; ma++) {
        #pragma unroll
        for (int na = 0; na < 4; na++) {
            long r0 = m0 + wm + ma * 16 + erow;
            long cc = n0 + wn + na * 8 + ecol;
            float2 v0 = { acc[ma][na][0], acc[ma][na][1] };
            float2 v1 = { acc[ma][na][2], acc[ma][na][3] };
            if (RES) {
                const float2 q0 = *(const float2*)&R[r0 * N + cc];
                const float2 q1 = *(const float2*)&R[(r0 + 8) * N + cc];
                v0.x += q0.x; v0.y += q0.y;
                v1.x += q1.x; v1.y += q1.y;
            }
            *(float2*)&C[r0 * N + cc] = v0;
            *(float2*)&C[(r0 + 8) * N + cc] = v1;
        }
    }
}

// ================= block reductions =================
__device__ __forceinline__ float block_sum(float v) {
    #pragma unroll
    for (int o = 16; o > 0; o >>= 1) v += __shfl_xor_sync(0xffffffffu, v, o);
    __shared__ float sh[8]; __shared__ float total;
    int w = threadIdx.x >> 5, l = threadIdx.x & 31;
    if (l == 0) sh[w] = v;
    __syncthreads();
    if (threadIdx.x == 0) { float s = 0.f; for (int i = 0; i < 8; i++) s += sh[i]; total = s; }
    __syncthreads();
    return total;
}
__device__ __forceinline__ float block_max(float v) {
    #pragma unroll
    for (int o = 16; o > 0; o >>= 1) v = fmaxf(v, __shfl_xor_sync(0xffffffffu, v, o));
    __shared__ float shm[8]; __shared__ float totalm;
    int w = threadIdx.x >> 5, l = threadIdx.x & 31;
    if (l == 0) shm[w] = v;
    __syncthreads();
    if (threadIdx.x == 0) { float s = -3.4e38f; for (int i = 0; i < 8; i++) s = fmaxf(s, shm[i]); totalm = s; }
    __syncthreads();
    return totalm;
}

// ================= elementwise =================
__device__ __forceinline__ void split_store(float v, __nv_bfloat16* hi, __nv_bfloat16* lo, long idx) {
    __nv_bfloat16 h = __float2bfloat16(v);
    hi[idx] = h;
    lo[idx] = __float2bfloat16(v - __bfloat162float(h));
}

__global__ void rmsnorm_bf16_kernel(const float* __restrict__ x, const float* __restrict__ w,
                                    __nv_bfloat16* __restrict__ hi, __nv_bfloat16* __restrict__ lo) {
    long row = blockIdx.x;
    const float* xr = x + row * HIDD;
    float s = 0.f;
    for (int i = threadIdx.x; i < HIDD; i += 256) { float v = xr[i]; s += v * v; }
    s = block_sum(s);
    float inv = rsqrtf(s / (float)HIDD + 1e-6f);
    for (int i = threadIdx.x; i < HIDD; i += 256)
        split_store(xr[i] * inv * w[i], hi, lo, row * HIDD + i);
}

__global__ void conv_hilo_kernel(const float* __restrict__ in,
                                 __nv_bfloat16* __restrict__ hi, __nv_bfloat16* __restrict__ lo, long n) {
    long idx = (long)blockIdx.x * 256 + threadIdx.x;
    if (idx < n) split_store(in[idx], hi, lo, idx);
}

__global__ void silu_bf16_kernel(const float* __restrict__ gu,
                                 __nv_bfloat16* __restrict__ hi, __nv_bfloat16* __restrict__ lo, long total) {
    long idx = (long)blockIdx.x * 256 + threadIdx.x;
    if (idx >= total) return;
    long row = idx / FFI;
    int  j   = (int)(idx - row * FFI);
    float g = gu[row * (2L * FFI) + j];
    float u = gu[row * (2L * FFI) + FFI + j];
    split_store((g / (1.f + expf(-g))) * u, hi, lo, idx);
}

// transpose-convert: W [K,N] fp32 -> T [N,K] bf16 hi/lo
__global__ void convT_kernel(const float* __restrict__ W,
                             __nv_bfloat16* __restrict__ Thi, __nv_bfloat16* __restrict__ Tlo,
                             int K, int N) {
    __shared__ float t[32][33];
    int n0 = blockIdx.x * 32, k0 = blockIdx.y * 32;
    for (int i = threadIdx.y; i < 32; i += 8)
        t[i][threadIdx.x] = W[(long)(k0 + i) * N + n0 + threadIdx.x];
    __syncthreads();
    for (int i = threadIdx.y; i < 32; i += 8) {
        float v = t[threadIdx.x][i];   // = W[k0+tx][n0+i]
        long o = (long)(n0 + i) * K + k0 + threadIdx.x;
        __nv_bfloat16 h = __float2bfloat16(v);
        Thi[o] = h;
        Tlo[o] = __float2bfloat16(v - __bfloat162float(h));
    }
}

__global__ void rope_kernel(float* __restrict__ qkv, const int* __restrict__ pos, int S) {
    long bs = blockIdx.x;
    int head = blockIdx.y;
    int i = threadIdx.x;
    int s = (int)(bs % S);
    float* base = qkv + bs * QKVW + (long)head * HD;
    float inv = powf(10000.f, -(float)i / 64.f);
    float ang = (float)pos[s] * inv;
    float sn, cs;
    sincosf(ang, &sn, &cs);
    float t1 = base[i], t2 = base[i + 64];
    base[i]      = t1 * cs - t2 * sn;
    base[i + 64] = t2 * cs + t1 * sn;
}

__global__ void softmax_kernel(float* __restrict__ sc, int S) {
    float* p = sc + (long)blockIdx.x * S;
    float mx = -3.4e38f;
    for (int i = threadIdx.x; i < S; i += 256) mx = fmaxf(mx, p[i]);
    mx = block_max(mx);
    float sum = 0.f;
    for (int i = threadIdx.x; i < S; i += 256) {
        float e = __expf(p[i] - mx);
        p[i] = e;
        sum += e;
    }
    sum = block_sum(sum);
    float r = 1.f / sum;
    for (int i = threadIdx.x; i < S; i += 256) p[i] *= r;
}

// ================= SIMT GEMM for attention (verified R1) =================
template<bool TRANSB, bool CAUSAL>
__global__ void __launch_bounds__(256, 2)
gemm128(const float* __restrict__ A, const float* __restrict__ B, float* __restrict__ C,
        int M, int N, int K, int lda, int ldb, int ldc,
        int Hn, int divB,
        long sAb, long sAh, long sBb, long sBh, long sCb, long sCh,
        float alpha)
{
    const int m0 = blockIdx.y * 128, n0 = blockIdx.x * 128;
    long offA = 0, offB = 0, offC = 0;
    {
        int z = blockIdx.z;
        int b = z / Hn, h = z - b * Hn;
        offA = b * sAb + (long)h * sAh;
        offB = b * sBb + (long)(h / divB) * sBh;
        offC = b * sCb + (long)h * sCh;
    }
    const int tx = threadIdx.x, ty = threadIdx.y;
    const int tid = ty * 16 + tx;

    if (CAUSAL && n0 >= m0 + 128) {
        #pragma unroll
        for (int i = 0; i < 8; i++) {
            long row = m0 + ty * 8 + i;
            #pragma unroll
            for (int j = 0; j < 8; j++)
                C[offC + row * ldc + n0 + tx * 8 + j] = NEGV;
        }
        return;
    }

    __shared__ float As[16][132];
    __shared__ float Bs[16][132];
    float acc[8][8];
    #pragma unroll
    for (int i = 0; i < 8; i++)
        #pragma unroll
        for (int j = 0; j < 8; j++) acc[i][j] = 0.f;

    const int ra = tid >> 2;
    const int ca = (tid & 3) * 4;
    const int rb = tid >> 5;
    const int cb4 = (tid & 31) * 4;

    for (int k0 = 0; k0 < K; k0 += 16) {
        float4 a0 = *(const float4*)&A[offA + (long)(m0 + ra) * lda + k0 + ca];
        float4 a1 = *(const float4*)&A[offA + (long)(m0 + ra + 64) * lda + k0 + ca];
        As[ca+0][ra] = a0.x; As[ca+1][ra] = a0.y; As[ca+2][ra] = a0.z; As[ca+3][ra] = a0.w;
        As[ca+0][ra+64] = a1.x; As[ca+1][ra+64] = a1.y; As[ca+2][ra+64] = a1.z; As[ca+3][ra+64] = a1.w;
        if (TRANSB) {
            float4 b0 = *(const float4*)&B[offB + (long)(n0 + ra) * ldb + k0 + ca];
            float4 b1 = *(const float4*)&B[offB + (long)(n0 + ra + 64) * ldb + k0 + ca];
            Bs[ca+0][ra] = b0.x; Bs[ca+1][ra] = b0.y; Bs[ca+2][ra] = b0.z; Bs[ca+3][ra] = b0.w;
            Bs[ca+0][ra+64] = b1.x; Bs[ca+1][ra+64] = b1.y; Bs[ca+2][ra+64] = b1.z; Bs[ca+3][ra+64] = b1.w;
        } else {
            float4 b0 = *(const float4*)&B[offB + (long)(k0 + rb) * ldb + n0 + cb4];
            float4 b1 = *(const float4*)&B[offB + (long)(k0 + rb + 8) * ldb + n0 + cb4];
            *(float4*)&Bs[rb][cb4] = b0;
            *(float4*)&Bs[rb + 8][cb4] = b1;
        }
        __syncthreads();
        #pragma unroll
        for (int kk = 0; kk < 16; kk++) {
            float a[8], b[8];
            *(float4*)&a[0] = *(const float4*)&As[kk][ty * 8];
            *(float4*)&a[4] = *(const float4*)&As[kk][ty * 8 + 4];
            *(float4*)&b[0] = *(const float4*)&Bs[kk][tx * 8];
            *(float4*)&b[4] = *(const float4*)&Bs[kk][tx * 8 + 4];
            #pragma unroll
            for (int i = 0; i < 8; i++)
                #pragma unroll
                for (int j = 0; j < 8; j++)
                    acc[i][j] = fmaf(a[i], b[j], acc[i][j]);
        }
        __syncthreads();
    }
    #pragma unroll
    for (int i = 0; i < 8; i++) {
        long row = m0 + ty * 8 + i;
        #pragma unroll
        for (int j = 0; j < 8; j++) {
            long col = n0 + tx * 8 + j;
            float v = acc[i][j] * alpha;
            if (CAUSAL && col > row) v = NEGV;
            C[offC + row * ldc + col] = v;
        }
    }
}

// ================= host launcher =================
extern "C" void kernel_launch(void* const* d_in, const int* in_sizes, int n_in,
                              void* d_out, int out_size) {
    const float* x         = (const float*)d_in[0];
    const float* ln1_w     = (const float*)d_in[1];
    const float* wqkv      = (const float*)d_in[2];
    const float* wo        = (const float*)d_in[3];
    const float* ln2_w     = (const float*)d_in[4];
    const float* w_gate_up = (const float*)d_in[5];
    const float* w_down    = (const float*)d_in[6];
    const int*   pos       = (const int*)d_in[7];
    float* out = (float*)d_out;

    const int S  = in_sizes[7];
    const long BS = (long)in_sizes[0] / HIDD;
    const int Bb = (int)(BS / S);

    float *pQKV, *pSC, *pAO, *pH1, *pGU;
    cudaGetSymbolAddress((void**)&pQKV, g_qkv);
    cudaGetSymbolAddress((void**)&pSC,  g_scores);
    cudaGetSymbolAddress((void**)&pAO,  g_attnout);
    cudaGetSymbolAddress((void**)&pH1,  g_h1);
    cudaGetSymbolAddress((void**)&pGU,  g_gu);
    __nv_bfloat16 *pHh,*pHl,*pAOh,*pAOl,*pACTh,*pACTl;
    __nv_bfloat16 *pQKVTh,*pQKVTl,*pWOTh,*pWOTl,*pGUTh,*pGUTl,*pDNTh,*pDNTl;
    cudaGetSymbolAddress((void**)&pHh, g_hh);     cudaGetSymbolAddress((void**)&pHl, g_hl);
    cudaGetSymbolAddress((void**)&pAOh, g_aoh);   cudaGetSymbolAddress((void**)&pAOl, g_aol);
    cudaGetSymbolAddress((void**)&pACTh, g_acth); cudaGetSymbolAddress((void**)&pACTl, g_actl);
    cudaGetSymbolAddress((void**)&pQKVTh, g_wqkvTh); cudaGetSymbolAddress((void**)&pQKVTl, g_wqkvTl);
    cudaGetSymbolAddress((void**)&pWOTh, g_woTh); cudaGetSymbolAddress((void**)&pWOTl, g_woTl);
    cudaGetSymbolAddress((void**)&pGUTh, g_guTh); cudaGetSymbolAddress((void**)&pGUTl, g_guTl);
    cudaGetSymbolAddress((void**)&pDNTh, g_dnTh); cudaGetSymbolAddress((void**)&pDNTl, g_dnTl);

    cudaFuncSetAttribute(hgemm<false>, cudaFuncAttributeMaxDynamicSharedMemorySize, HG_SMEM);
    cudaFuncSetAttribute(hgemm<true>,  cudaFuncAttributeMaxDynamicSharedMemorySize, HG_SMEM);

    dim3 blk16(16, 16), blkT(32, 8);
    const float inv_sqrt_d = 0.08838834764831843f;

    // weight transpose+convert (bf16 hi/lo, [N,K])
    convT_kernel<<<dim3(QKVW/32,  HIDD/32), blkT>>>(wqkv,      pQKVTh, pQKVTl, HIDD, QKVW);
    convT_kernel<<<dim3(HIDD/32,  HIDD/32), blkT>>>(wo,        pWOTh,  pWOTl,  HIDD, HIDD);
    convT_kernel<<<dim3(2*FFI/32, HIDD/32), blkT>>>(w_gate_up, pGUTh,  pGUTl,  HIDD, 2*FFI);
    convT_kernel<<<dim3(HIDD/32,  FFI/32),  blkT>>>(w_down,    pDNTh,  pDNTl,  FFI,  HIDD);

    // 1. h = rmsnorm(x) -> bf16 hi/lo
    rmsnorm_bf16_kernel<<<(int)BS, 256>>>(x, ln1_w, pHh, pHl);

    // 2. qkv = h @ wqkv  (HMMA)
    hgemm<false><<<dim3((int)(BS/128), QKVW/128), 256, HG_SMEM>>>(
        pHh, pHl, pQKVTh, pQKVTl, nullptr, pQKV, HIDD, QKVW);

    // 3. rope
    rope_kernel<<<dim3((unsigned)BS, NH + NKV), 64>>>(pQKV, pos, S);

    // 4. scores = QK^T / sqrt(D), causal (SIMT)
    gemm128<true, true><<<dim3(S/128, S/128, Bb*NH), blk16>>>(
        pQKV, pQKV + NH*HD, pSC,
        S, S, HD, QKVW, QKVW, S, NH, NH/NKV,
        (long)S*QKVW, HD, (long)S*QKVW, HD, (long)NH*S*S, (long)S*S,
        inv_sqrt_d);

    // 5. softmax
    softmax_kernel<<<(unsigned)(Bb*NH*S), 256>>>(pSC, S);

    // 6. O = P @ V (SIMT) -> [b,s,h,d]
    gemm128<false, false><<<dim3(HD/128, S/128, Bb*NH), blk16>>>(
        pSC, pQKV + (NH+NKV)*HD, pAO,
        S, HD, S, S, QKVW, HIDD, NH, NH/NKV,
        (long)NH*S*S, (long)S*S, (long)S*QKVW, HD, (long)S*HIDD, HD,
        1.f);

    // 6b. convert attnout -> bf16 hi/lo
    conv_hilo_kernel<<<(unsigned)((BS*HIDD + 255)/256), 256>>>(pAO, pAOh, pAOl, BS*HIDD);

    // 7. h1 = x + attnout @ wo  (HMMA, fused residual)
    hgemm<true><<<dim3((int)(BS/128), HIDD/128), 256, HG_SMEM>>>(
        pAOh, pAOl, pWOTh, pWOTl, x, pH1, HIDD, HIDD);

    // 8. h2 = rmsnorm(h1) -> bf16 hi/lo
    rmsnorm_bf16_kernel<<<(int)BS, 256>>>(pH1, ln2_w, pHh, pHl);

    // 9. gu = h2 @ w_gate_up  (HMMA)
    hgemm<false><<<dim3((int)(BS/128), 2*FFI/128), 256, HG_SMEM>>>(
        pHh, pHl, pGUTh, pGUTl, nullptr, pGU, HIDD, 2*FFI);

    // 10. act = silu(gate)*up -> bf16 hi/lo
    long total = BS * FFI;
    silu_bf16_kernel<<<(unsigned)((total + 255)/256), 256>>>(pGU, pACTh, pACTl, total);

    // 11. out = h1 + act @ w_down  (HMMA, fused residual)
    hgemm<true><<<dim3((int)(BS/128), HIDD/128), 256, HG_SMEM>>>(
        pACTh, pACTl, pDNTh, pDNTl, pH1, out, FFI, HIDD);
}

// round 6
// speedup vs baseline: 1.1086x; 1.1086x over previous
#include <cuda_runtime.h>
#include <cuda_bf16.h>
#include <math.h>
#include <stdint.h>

#define NH   16
#define NKV  4
#define HD   128
#define HIDD 2048
#define FFI  8192
#define QKVW ((NH + 2*NKV) * HD)   /* 3072 */

// ================= scratch (B=4, S=1024) =================
static __device__ float g_qkv[4096L * QKVW];
static __device__ float g_scores[(long)4 * NH * 1024 * 1024];
static __device__ float g_h1[4096L * HIDD];
static __device__ float g_gu[4096L * 2 * FFI];

static __device__ __nv_bfloat16 g_hh[4096L * HIDD],  g_hl[4096L * HIDD];
static __device__ __nv_bfloat16 g_aoh[4096L * HIDD], g_aol[4096L * HIDD];
static __device__ __nv_bfloat16 g_acth[4096L * FFI], g_actl[4096L * FFI];
static __device__ __nv_bfloat16 g_qh[(long)4*NH*1024*HD], g_ql[(long)4*NH*1024*HD];
static __device__ __nv_bfloat16 g_kh[(long)4*NKV*1024*HD], g_kl[(long)4*NKV*1024*HD];
static __device__ __nv_bfloat16 g_vth[(long)4*NKV*HD*1024], g_vtl[(long)4*NKV*HD*1024];
static __device__ __nv_bfloat16 g_ph[(long)4*NH*1024*1024], g_pl[(long)4*NH*1024*1024];
static __device__ __nv_bfloat16 g_wqkvTh[(long)QKVW * HIDD], g_wqkvTl[(long)QKVW * HIDD];
static __device__ __nv_bfloat16 g_woTh[(long)HIDD * HIDD],   g_woTl[(long)HIDD * HIDD];
static __device__ __nv_bfloat16 g_guTh[(long)2*FFI * HIDD],  g_guTl[(long)2*FFI * HIDD];
static __device__ __nv_bfloat16 g_dnTh[(long)HIDD * FFI],    g_dnTl[(long)HIDD * FFI];

// ================= PTX helpers =================
__device__ __forceinline__ uint32_t smem_u32(const void* p) {
    uint32_t a;
    asm("{ .reg .u64 t; cvta.to.shared.u64 t, %1; cvt.u32.u64 %0, t; }" : "=r"(a) : "l"(p));
    return a;
}
__device__ __forceinline__ void cp16(uint32_t dst, const void* src) {
    asm volatile("cp.async.cg.shared.global [%0], [%1], 16;" :: "r"(dst), "l"(src));
}
__device__ __forceinline__ void cp_commit() { asm volatile("cp.async.commit_group;"); }
__device__ __forceinline__ void cp_wait1() { asm volatile("cp.async.wait_group 1;"); }
__device__ __forceinline__ void cp_wait0() { asm volatile("cp.async.wait_group 0;"); }

__device__ __forceinline__ void ldm_x4(uint32_t* r, uint32_t addr) {
    asm volatile("ldmatrix.sync.aligned.m8n8.x4.shared.b16 {%0,%1,%2,%3}, [%4];"
        : "=r"(r[0]), "=r"(r[1]), "=r"(r[2]), "=r"(r[3]) : "r"(addr));
}
__device__ __forceinline__ void mma16816(float* d, const uint32_t* a, const uint32_t* b) {
    asm volatile("mma.sync.aligned.m16n8k16.row.col.f32.bf16.bf16.f32 "
        "{%0,%1,%2,%3}, {%4,%5,%6,%7}, {%8,%9}, {%0,%1,%2,%3};"
        : "+f"(d[0]), "+f"(d[1]), "+f"(d[2]), "+f"(d[3])
        : "r"(a[0]), "r"(a[1]), "r"(a[2]), "r"(a[3]), "r"(b[0]), "r"(b[1]));
}

__device__ __forceinline__ void split_store(float v, __nv_bfloat16* hi, __nv_bfloat16* lo, long idx) {
    __nv_bfloat16 h = __float2bfloat16(v);
    hi[idx] = h;
    lo[idx] = __float2bfloat16(v - __bfloat162float(h));
}

// ================= HMMA TN GEMM (bf16x3, fp32 accum) =================
// C[M,N] = alpha * Ahi/lo[M,K] x (Bhi/lo[N,K])^T  (+ residual R)
// MODE 0: weights (fp32 out, optional residual, block swizzle)
// MODE 1: QK^T    (fp32 out, causal tile skip, per-head batch via z)
// MODE 2: PV      (bf16 hi/lo out, K truncated by causality, per-head batch)
#define SAS 72
#define TILEB (128 * SAS * 2)
#define STAGE (4 * TILEB)
#define HG_SMEM (2 * STAGE)

template<int MODE, bool RES>
__global__ void __launch_bounds__(256, 1)
hgemm(const __nv_bfloat16* __restrict__ Ahi, const __nv_bfloat16* __restrict__ Alo,
      const __nv_bfloat16* __restrict__ Bhi, const __nv_bfloat16* __restrict__ Blo,
      const float* __restrict__ R, float* __restrict__ Cf,
      __nv_bfloat16* __restrict__ Chi, __nv_bfloat16* __restrict__ Clo,
      int K, int ldc, long sA, long sB, long sCb, long sCh, float alpha)
{
    extern __shared__ char sm[];
    const uint32_t sbase = smem_u32(sm);
    const int tid = threadIdx.x;

    int m0, n0;
    if (MODE == 0) {
        // swizzle: groups of 8 N-tiles, M sweeps inside a group (L2/HBM reuse)
        int lin = blockIdx.y * gridDim.x + blockIdx.x;
        int grpSize = gridDim.x * 8;
        int grp = lin / grpSize, rem = lin % grpSize;
        m0 = (rem >> 3) * 128;
        n0 = (grp * 8 + (rem & 7)) * 128;
    } else {
        m0 = blockIdx.x * 128;
        n0 = blockIdx.y * 128;
    }
    if (MODE == 1 && n0 > m0) return;

    const int z = blockIdx.z;
    const long offA = (long)z * sA;
    const long offB = (long)(z >> 2) * sB;
    const long offC = (long)(z >> 4) * sCb + (long)(z & 15) * sCh;

    int NB = K >> 6;
    if (MODE == 2) { int nbe = (m0 >> 6) + 2; if (nbe < NB) NB = nbe; }

    const int wid = tid >> 5, lane = tid & 31;
    const int wm = (wid >> 2) * 64;
    const int wn = (wid & 3) * 32;

    const __nv_bfloat16* srcs[4] = {
        Ahi + offA + (long)m0 * K, Alo + offA + (long)m0 * K,
        Bhi + offB + (long)n0 * K, Blo + offB + (long)n0 * K };

    const int alr = lane & 15, alc = (lane >> 4) * 8;
    const int blr = lane & 7;
    const int bhalf = (lane >> 3) & 1;
    const int bquad = (lane >> 4) * 8;

    float acc[4][4][4];
    #pragma unroll
    for (int i = 0; i < 4; i++)
        #pragma unroll
        for (int j = 0; j < 4; j++)
            #pragma unroll
            for (int q = 0; q < 4; q++) acc[i][j][q] = 0.f;

    auto load_stage = [&](int s, int blk) {
        const long kb = (long)blk << 6;
        #pragma unroll
        for (int t = 0; t < 4; t++) {
            const __nv_bfloat16* S = srcs[t] + kb;
            const uint32_t dbase = sbase + s * STAGE + t * TILEB;
            #pragma unroll
            for (int i = 0; i < 4; i++) {
                int idx = tid + 256 * i;
                int r = idx >> 3, c = idx & 7;
                cp16(dbase + (r * SAS + c * 8) * 2, S + (long)r * K + c * 8);
            }
        }
        cp_commit();
    };

    load_stage(0, 0);

    for (int blk = 0; blk < NB; blk++) {
        const int s = blk & 1;
        if (blk + 1 < NB) { load_stage(s ^ 1, blk + 1); cp_wait1(); }
        else              { cp_wait0(); }
        __syncthreads();

        const uint32_t sAh = sbase + s * STAGE;
        const uint32_t sAl = sAh + TILEB;
        const uint32_t sBh = sAh + 2 * TILEB;
        const uint32_t sBl = sAh + 3 * TILEB;

        #pragma unroll
        for (int kt = 0; kt < 4; kt++) {
            uint32_t ah[4][4], al[4][4], bh[4][2], bl[4][2];
            #pragma unroll
            for (int ma = 0; ma < 4; ma++) {
                uint32_t ao = ((wm + ma * 16 + alr) * SAS + kt * 16 + alc) * 2;
                ldm_x4(ah[ma], sAh + ao);
                ldm_x4(al[ma], sAl + ao);
            }
            #pragma unroll
            for (int np = 0; np < 2; np++) {
                uint32_t bo = ((wn + np * 16 + bquad + blr) * SAS + kt * 16 + bhalf * 8) * 2;
                uint32_t t4[4];
                ldm_x4(t4, sBh + bo);
                bh[np*2+0][0] = t4[0]; bh[np*2+0][1] = t4[1];
                bh[np*2+1][0] = t4[2]; bh[np*2+1][1] = t4[3];
                ldm_x4(t4, sBl + bo);
                bl[np*2+0][0] = t4[0]; bl[np*2+0][1] = t4[1];
                bl[np*2+1][0] = t4[2]; bl[np*2+1][1] = t4[3];
            }
            #pragma unroll
            for (int ma = 0; ma < 4; ma++)
                #pragma unroll
                for (int na = 0; na < 4; na++) {
                    mma16816(acc[ma][na], ah[ma], bh[na]);
                    mma16816(acc[ma][na], ah[ma], bl[na]);
                    mma16816(acc[ma][na], al[ma], bh[na]);
                }
        }
        __syncthreads();
    }

    // epilogue
    const int erow = lane >> 2, ecol = (lane & 3) * 2;
    #pragma unroll
    for (int ma = 0; ma < 4; ma++) {
        #pragma unroll
        for (int na = 0; na < 4; na++) {
            long r0 = m0 + wm + ma * 16 + erow;
            long cc = n0 + wn + na * 8 + ecol;
            float v00 = acc[ma][na][0] * alpha, v01 = acc[ma][na][1] * alpha;
            float v10 = acc[ma][na][2] * alpha, v11 = acc[ma][na][3] * alpha;
            if (MODE == 2) {
                long o0 = offC + r0 * ldc + cc;
                long o1 = offC + (r0 + 8) * ldc + cc;
                split_store(v00, Chi, Clo, o0);
                split_store(v01, Chi, Clo, o0 + 1);
                split_store(v10, Chi, Clo, o1);
                split_store(v11, Chi, Clo, o1 + 1);
            } else {
                if (RES) {
                    const float2 q0 = *(const float2*)&R[offC + r0 * ldc + cc];
                    const float2 q1 = *(const float2*)&R[offC + (r0 + 8) * ldc + cc];
                    v00 += q0.x; v01 += q0.y; v10 += q1.x; v11 += q1.y;
                }
                float2 w0 = {v00, v01}, w1 = {v10, v11};
                *(float2*)&Cf[offC + r0 * ldc + cc] = w0;
                *(float2*)&Cf[offC + (r0 + 8) * ldc + cc] = w1;
            }
        }
    }
}

// ================= block reductions =================
__device__ __forceinline__ float block_sum(float v) {
    #pragma unroll
    for (int o = 16; o > 0; o >>= 1) v += __shfl_xor_sync(0xffffffffu, v, o);
    __shared__ float sh[8]; __shared__ float total;
    int w = threadIdx.x >> 5, l = threadIdx.x & 31;
    if (l == 0) sh[w] = v;
    __syncthreads();
    if (threadIdx.x == 0) { float s = 0.f; for (int i = 0; i < 8; i++) s += sh[i]; total = s; }
    __syncthreads();
    return total;
}
__device__ __forceinline__ float block_max(float v) {
    #pragma unroll
    for (int o = 16; o > 0; o >>= 1) v = fmaxf(v, __shfl_xor_sync(0xffffffffu, v, o));
    __shared__ float shm[8]; __shared__ float totalm;
    int w = threadIdx.x >> 5, l = threadIdx.x & 31;
    if (l == 0) shm[w] = v;
    __syncthreads();
    if (threadIdx.x == 0) { float s = -3.4e38f; for (int i = 0; i < 8; i++) s = fmaxf(s, shm[i]); totalm = s; }
    __syncthreads();
    return totalm;
}

// ================= elementwise =================
__global__ void rmsnorm_bf16_kernel(const float* __restrict__ x, const float* __restrict__ w,
                                    __nv_bfloat16* __restrict__ hi, __nv_bfloat16* __restrict__ lo) {
    long row = blockIdx.x;
    const float* xr = x + row * HIDD;
    float s = 0.f;
    for (int i = threadIdx.x; i < HIDD; i += 256) { float v = xr[i]; s += v * v; }
    s = block_sum(s);
    float inv = rsqrtf(s / (float)HIDD + 1e-6f);
    for (int i = threadIdx.x; i < HIDD; i += 256)
        split_store(xr[i] * inv * w[i], hi, lo, row * HIDD + i);
}

__global__ void silu_bf16_kernel(const float* __restrict__ gu,
                                 __nv_bfloat16* __restrict__ hi, __nv_bfloat16* __restrict__ lo, long total) {
    long idx = (long)blockIdx.x * 256 + threadIdx.x;
    if (idx >= total) return;
    long row = idx / FFI;
    int  j   = (int)(idx - row * FFI);
    float g = gu[row * (2L * FFI) + j];
    float u = gu[row * (2L * FFI) + FFI + j];
    split_store((g / (1.f + expf(-g))) * u, hi, lo, idx);
}

// transpose-convert: W [K,N] fp32 -> T [N,K] bf16 hi/lo
__global__ void convT_kernel(const float* __restrict__ W,
                             __nv_bfloat16* __restrict__ Thi, __nv_bfloat16* __restrict__ Tlo,
                             int K, int N) {
    __shared__ float t[32][33];
    int n0 = blockIdx.x * 32, k0 = blockIdx.y * 32;
    for (int i = threadIdx.y; i < 32; i += 8)
        t[i][threadIdx.x] = W[(long)(k0 + i) * N + n0 + threadIdx.x];
    __syncthreads();
    for (int i = threadIdx.y; i < 32; i += 8) {
        float v = t[threadIdx.x][i];
        long o = (long)(n0 + i) * K + k0 + threadIdx.x;
        __nv_bfloat16 h = __float2bfloat16(v);
        Thi[o] = h;
        Tlo[o] = __float2bfloat16(v - __bfloat162float(h));
    }
}

// rope + split q,k: qkv fp32 [b,s,3072] -> qh/ql [b,h,s,128], kh/kl [b,hk,s,128]
__global__ void conv_qk_kernel(const float* __restrict__ qkv, const int* __restrict__ pos,
                               __nv_bfloat16* __restrict__ qh, __nv_bfloat16* __restrict__ ql,
                               __nv_bfloat16* __restrict__ kh, __nv_bfloat16* __restrict__ kl,
                               int S) {
    long idx = (long)blockIdx.x * 256 + threadIdx.x;   // total B*S*20*64
    int d = (int)(idx & 63);
    long t = idx >> 6;
    int head = (int)(t % (NH + NKV)); t /= (NH + NKV);
    int s = (int)(t % S);
    int b = (int)(t / S);
    const float* base = qkv + ((long)(b * S + s)) * QKVW + head * HD;
    float t1 = base[d], t2 = base[d + 64];
    float invf = powf(10000.f, -(float)d / 64.f);
    float ang = (float)pos[s] * invf;
    float sn, cs;
    sincosf(ang, &sn, &cs);
    float r1 = t1 * cs - t2 * sn;
    float r2 = t2 * cs + t1 * sn;
    if (head < NH) {
        long o = ((long)(b * NH + head) * S + s) * HD;
        split_store(r1, qh, ql, o + d);
        split_store(r2, qh, ql, o + d + 64);
    } else {
        long o = ((long)(b * NKV + head - NH) * S + s) * HD;
        split_store(r1, kh, kl, o + d);
        split_store(r2, kh, kl, o + d + 64);
    }
}

// v transpose + split: qkv v slice [b,s,hk,128] -> vt [b,hk,d,s]
__global__ void conv_vt_kernel(const float* __restrict__ qkv,
                               __nv_bfloat16* __restrict__ vth, __nv_bfloat16* __restrict__ vtl,
                               int S) {
    __shared__ float t[32][33];
    int s0 = blockIdx.x * 32, d0 = blockIdx.y * 32;
    int z = blockIdx.z;                 // b*NKV + h
    int b = z >> 2, h = z & 3;
    for (int i = threadIdx.y; i < 32; i += 8)
        t[i][threadIdx.x] = qkv[((long)(b * S + s0 + i)) * QKVW + (NH + NKV + h) * HD + d0 + threadIdx.x];
    __syncthreads();
    for (int i = threadIdx.y; i < 32; i += 8) {
        float v = t[threadIdx.x][i];    // = v[s0+tx][d0+i]
        long o = ((long)z * HD + d0 + i) * S + s0 + threadIdx.x;
        split_store(v, vth, vtl, o);
    }
}

// causal softmax: reads fp32 scores row, writes P as bf16 hi/lo (zeros above diag)
__global__ void softmax_split_kernel(const float* __restrict__ sc,
                                     __nv_bfloat16* __restrict__ ph, __nv_bfloat16* __restrict__ pl,
                                     int S) {
    long row = blockIdx.x;
    int r = (int)(row & (S - 1));
    int len = r + 1;
    const float* p = sc + row * (long)S;
    float mx = -3.4e38f;
    for (int i = threadIdx.x; i < len; i += 256) mx = fmaxf(mx, p[i]);
    mx = block_max(mx);
    float sum = 0.f;
    for (int i = threadIdx.x; i < len; i += 256) sum += __expf(p[i] - mx);
    sum = block_sum(sum);
    float rinv = 1.f / sum;
    long o = row * (long)S;
    for (int i = threadIdx.x; i < len; i += 256)
        split_store(__expf(p[i] - mx) * rinv, ph, pl, o + i);
    __nv_bfloat16 z = __float2bfloat16(0.f);
    for (int i = len + (int)threadIdx.x - (len & 255) + ((len & 255) ? 0 : 0); false;) {}
    for (int i = len + threadIdx.x; i < S; i += 256) { ph[o + i] = z; pl[o + i] = z; }
}

// ================= host launcher =================
extern "C" void kernel_launch(void* const* d_in, const int* in_sizes, int n_in,
                              void* d_out, int out_size) {
    const float* x         = (const float*)d_in[0];
    const float* ln1_w     = (const float*)d_in[1];
    const float* wqkv      = (const float*)d_in[2];
    const float* wo        = (const float*)d_in[3];
    const float* ln2_w     = (const float*)d_in[4];
    const float* w_gate_up = (const float*)d_in[5];
    const float* w_down    = (const float*)d_in[6];
    const int*   pos       = (const int*)d_in[7];
    float* out = (float*)d_out;

    const int S  = in_sizes[7];                 // 1024
    const long BS = (long)in_sizes[0] / HIDD;   // 4096
    const int Bb = (int)(BS / S);               // 4

    float *pQKV, *pSC, *pH1, *pGU;
    cudaGetSymbolAddress((void**)&pQKV, g_qkv);
    cudaGetSymbolAddress((void**)&pSC,  g_scores);
    cudaGetSymbolAddress((void**)&pH1,  g_h1);
    cudaGetSymbolAddress((void**)&pGU,  g_gu);
    __nv_bfloat16 *pHh,*pHl,*pAOh,*pAOl,*pACTh,*pACTl;
    __nv_bfloat16 *pQh,*pQl,*pKh,*pKl,*pVth,*pVtl,*pPh,*pPl;
    __nv_bfloat16 *pQKVTh,*pQKVTl,*pWOTh,*pWOTl,*pGUTh,*pGUTl,*pDNTh,*pDNTl;
    cudaGetSymbolAddress((void**)&pHh, g_hh);     cudaGetSymbolAddress((void**)&pHl, g_hl);
    cudaGetSymbolAddress((void**)&pAOh, g_aoh);   cudaGetSymbolAddress((void**)&pAOl, g_aol);
    cudaGetSymbolAddress((void**)&pACTh, g_acth); cudaGetSymbolAddress((void**)&pACTl, g_actl);
    cudaGetSymbolAddress((void**)&pQh, g_qh);     cudaGetSymbolAddress((void**)&pQl, g_ql);
    cudaGetSymbolAddress((void**)&pKh, g_kh);     cudaGetSymbolAddress((void**)&pKl, g_kl);
    cudaGetSymbolAddress((void**)&pVth, g_vth);   cudaGetSymbolAddress((void**)&pVtl, g_vtl);
    cudaGetSymbolAddress((void**)&pPh, g_ph);     cudaGetSymbolAddress((void**)&pPl, g_pl);
    cudaGetSymbolAddress((void**)&pQKVTh, g_wqkvTh); cudaGetSymbolAddress((void**)&pQKVTl, g_wqkvTl);
    cudaGetSymbolAddress((void**)&pWOTh, g_woTh); cudaGetSymbolAddress((void**)&pWOTl, g_woTl);
    cudaGetSymbolAddress((void**)&pGUTh, g_guTh); cudaGetSymbolAddress((void**)&pGUTl, g_guTl);
    cudaGetSymbolAddress((void**)&pDNTh, g_dnTh); cudaGetSymbolAddress((void**)&pDNTl, g_dnTl);

    cudaFuncSetAttribute(hgemm<0,false>, cudaFuncAttributeMaxDynamicSharedMemorySize, HG_SMEM);
    cudaFuncSetAttribute(hgemm<0,true>,  cudaFuncAttributeMaxDynamicSharedMemorySize, HG_SMEM);
    cudaFuncSetAttribute(hgemm<1,false>, cudaFuncAttributeMaxDynamicSharedMemorySize, HG_SMEM);
    cudaFuncSetAttribute(hgemm<2,false>, cudaFuncAttributeMaxDynamicSharedMemorySize, HG_SMEM);

    dim3 blkT(32, 8);
    const float inv_sqrt_d = 0.08838834764831843f;

    // weight transpose+convert
    convT_kernel<<<dim3(QKVW/32,  HIDD/32), blkT>>>(wqkv,      pQKVTh, pQKVTl, HIDD, QKVW);
    convT_kernel<<<dim3(HIDD/32,  HIDD/32), blkT>>>(wo,        pWOTh,  pWOTl,  HIDD, HIDD);
    convT_kernel<<<dim3(2*FFI/32, HIDD/32), blkT>>>(w_gate_up, pGUTh,  pGUTl,  HIDD, 2*FFI);
    convT_kernel<<<dim3(HIDD/32,  FFI/32),  blkT>>>(w_down,    pDNTh,  pDNTl,  FFI,  HIDD);

    // 1. h = rmsnorm(x)
    rmsnorm_bf16_kernel<<<(int)BS, 256>>>(x, ln1_w, pHh, pHl);

    // 2. qkv = h @ wqkv
    hgemm<0,false><<<dim3((int)(BS/128), QKVW/128, 1), 256, HG_SMEM>>>(
        pHh, pHl, pQKVTh, pQKVTl, nullptr, pQKV, nullptr, nullptr,
        HIDD, QKVW, 0, 0, 0, 0, 1.f);

    // 3. rope + split q,k ; transpose + split v
    conv_qk_kernel<<<(unsigned)((BS * (NH+NKV) * 64) / 256), 256>>>(pQKV, pos, pQh, pQl, pKh, pKl, S);
    conv_vt_kernel<<<dim3(S/32, HD/32, Bb*NKV), blkT>>>(pQKV, pVth, pVtl, S);

    // 4. scores = QK^T/sqrt(D) (causal tiles only)
    hgemm<1,false><<<dim3(S/128, S/128, Bb*NH), 256, HG_SMEM>>>(
        pQh, pQl, pKh, pKl, nullptr, pSC, nullptr, nullptr,
        HD, S, (long)S*HD, (long)S*HD, (long)NH*S*S, (long)S*S, inv_sqrt_d);

    // 5. softmax -> P bf16 hi/lo
    softmax_split_kernel<<<(unsigned)(Bb*NH*S), 256>>>(pSC, pPh, pPl, S);

    // 6. attnout = P @ V  -> bf16 hi/lo [b,s,h*d]
    hgemm<2,false><<<dim3(S/128, 1, Bb*NH), 256, HG_SMEM>>>(
        pPh, pPl, pVth, pVtl, nullptr, nullptr, pAOh, pAOl,
        S, HIDD, (long)S*S, (long)HD*S, (long)S*HIDD, HD, 1.f);

    // 7. h1 = x + attnout @ wo
    hgemm<0,true><<<dim3((int)(BS/128), HIDD/128, 1), 256, HG_SMEM>>>(
        pAOh, pAOl, pWOTh, pWOTl, x, pH1, nullptr, nullptr,
        HIDD, HIDD, 0, 0, 0, 0, 1.f);

    // 8. h2 = rmsnorm(h1)
    rmsnorm_bf16_kernel<<<(int)BS, 256>>>(pH1, ln2_w, pHh, pHl);

    // 9. gu = h2 @ w_gate_up
    hgemm<0,false><<<dim3((int)(BS/128), 2*FFI/128, 1), 256, HG_SMEM>>>(
        pHh, pHl, pGUTh, pGUTl, nullptr, pGU, nullptr, nullptr,
        HIDD, 2*FFI, 0, 0, 0, 0, 1.f);

    // 10. act = silu(gate)*up
    long total = BS * FFI;
    silu_bf16_kernel<<<(unsigned)((total + 255)/256), 256>>>(pGU, pACTh, pACTl, total);

    // 11. out = h1 + act @ w_down
    hgemm<0,true><<<dim3((int)(BS/128), HIDD/128, 1), 256, HG_SMEM>>>(
        pACTh, pACTl, pDNTh, pDNTl, pH1, out, nullptr, nullptr,
        FFI, HIDD, 0, 0, 0, 0, 1.f);
}